// round 1
// baseline (speedup 1.0000x reference)
#include <cuda_runtime.h>
#include <cstdint>
#include <math.h>

#define HD 512
#define BB 128
#define SSQ 2048
#define TSR 16    // s-rows per scores block
#define NTH 256   // threads in scores kernel; thread t owns o = 2t, 2t+1

// -------- device scratch (no allocations allowed) --------
__device__ float g_WaT[HD * HD];
__device__ float g_UaT[HD * HD];
__device__ float g_c[BB * HD];
__device__ float g_scores[BB * SSQ];

// -------- f32x2 helpers (Blackwell packed fp32) --------
__device__ __forceinline__ unsigned long long pack2(float lo, float hi) {
    unsigned long long r;
    asm("mov.b64 %0, {%1, %2};" : "=l"(r) : "f"(lo), "f"(hi));
    return r;
}
__device__ __forceinline__ void fma2(unsigned long long& d, unsigned long long a,
                                     unsigned long long b) {
    asm("fma.rn.f32x2 %0, %1, %2, %0;" : "+l"(d) : "l"(a), "l"(b));
}
__device__ __forceinline__ float2 unpack2(unsigned long long v) {
    float2 f;
    asm("mov.b64 {%0, %1}, %2;" : "=f"(f.x), "=f"(f.y) : "l"(v));
    return f;
}

// -------- 512x512 transpose: out[h][o] = in[o][h] --------
__global__ void transpose512(const float* __restrict__ in, int which) {
    __shared__ float tile[32][33];
    float* out = which ? g_UaT : g_WaT;
    int bx = blockIdx.x * 32, by = blockIdx.y * 32;
    int tx = threadIdx.x, ty = threadIdx.y;  // (32, 8)
#pragma unroll
    for (int i = 0; i < 32; i += 8)
        tile[ty + i][tx] = in[(size_t)(by + ty + i) * HD + bx + tx];
    __syncthreads();
#pragma unroll
    for (int i = 0; i < 32; i += 8)
        out[(size_t)(bx + ty + i) * HD + by + tx] = tile[tx][ty + i];
}

// -------- c[b][o] = sum_h query[b][h]*Wa[o][h] + ba[o] + bu[o] --------
__global__ void c_kernel(const float* __restrict__ query, const float* __restrict__ ba,
                         const float* __restrict__ bu) {
    int b = blockIdx.x;
    int o = threadIdx.x;  // 512 threads
    __shared__ float q[HD];
    q[o] = query[(size_t)b * HD + o];
    __syncthreads();
    float acc = ba[o] + bu[o];
#pragma unroll 8
    for (int h = 0; h < HD; h++) acc += q[h] * g_WaT[(size_t)h * HD + o];
    g_c[(size_t)b * HD + o] = acc;
}

// -------- fused scores: score[b][s] = Va . tanh(c[b] + keys[b][s] @ Ua^T) + bv ----
__global__ void __launch_bounds__(NTH)
scores_kernel(const float* __restrict__ keys, const float* __restrict__ Va,
              const float* __restrict__ bvp) {
    int b = blockIdx.y;
    int s0 = blockIdx.x * TSR;
    int t = threadIdx.x;

    extern __shared__ unsigned long long skd[];  // [TSR][HD] of {k,k} pairs = 64KB

    // Load keys tile, duplicating each value into both f32x2 lanes.
    const float4* kg = (const float4*)(keys + ((size_t)b * SSQ + s0) * HD);
#pragma unroll
    for (int i = t; i < TSR * HD / 4; i += NTH) {
        float4 v = kg[i];
        unsigned long long* dst = &skd[(size_t)i * 4];
        dst[0] = pack2(v.x, v.x);
        dst[1] = pack2(v.y, v.y);
        dst[2] = pack2(v.z, v.z);
        dst[3] = pack2(v.w, v.w);
    }
    __syncthreads();

    int o = 2 * t;
    // acc init: c[b][o], c[b][o+1] are adjacent floats -> load directly as the pair
    unsigned long long cini = *(const unsigned long long*)(g_c + (size_t)b * HD + o);
    unsigned long long acc[TSR];
#pragma unroll
    for (int s = 0; s < TSR; s++) acc[s] = cini;

    // UaT[h][o..o+1] is an adjacent float pair in memory == ready f32x2 operand.
    const unsigned long long* uaP = (const unsigned long long*)g_UaT;  // idx h*(HD/2)+t
#pragma unroll 2
    for (int h = 0; h < HD; h += 4) {
        unsigned long long u0 = uaP[(size_t)(h + 0) * (HD / 2) + t];
        unsigned long long u1 = uaP[(size_t)(h + 1) * (HD / 2) + t];
        unsigned long long u2 = uaP[(size_t)(h + 2) * (HD / 2) + t];
        unsigned long long u3 = uaP[(size_t)(h + 3) * (HD / 2) + t];
#pragma unroll
        for (int s = 0; s < TSR; s++) {
            const unsigned long long* kr = &skd[(size_t)s * HD + h];
            ulonglong2 k01 = *(const ulonglong2*)(kr);
            ulonglong2 k23 = *(const ulonglong2*)(kr + 2);
            fma2(acc[s], u0, k01.x);
            fma2(acc[s], u1, k01.y);
            fma2(acc[s], u2, k23.x);
            fma2(acc[s], u3, k23.y);
        }
    }

    // Epilogue: per-thread Va-weighted tanh partial, then block reduce per s-row.
    __syncthreads();
    float* red = (float*)skd;  // TSR*NTH floats = 16KB, fits
    float2 va = *(const float2*)(Va + o);
    float bvv = bvp[0];
#pragma unroll
    for (int s = 0; s < TSR; s++) {
        float2 av = unpack2(acc[s]);
        red[s * NTH + t] = va.x * tanhf(av.x) + va.y * tanhf(av.y);
    }
    __syncthreads();
    int lane = t & 31, w = t >> 5;
    for (int rr = w; rr < TSR; rr += NTH / 32) {
        const float* row = red + rr * NTH;
        float v = row[lane] + row[lane + 32] + row[lane + 64] + row[lane + 96] +
                  row[lane + 128] + row[lane + 160] + row[lane + 192] + row[lane + 224];
#pragma unroll
        for (int off = 16; off; off >>= 1) v += __shfl_xor_sync(0xffffffffu, v, off);
        if (lane == 0) g_scores[(size_t)b * SSQ + s0 + rr] = v + bvv;
    }
}

// -------- softmax over S per batch; weights -> g_scores (and d_out) --------
__global__ void softmax_kernel(float* __restrict__ wout) {
    int b = blockIdx.x, t = threadIdx.x;  // 256 threads
    __shared__ float sred[64];
    float* sc = g_scores + (size_t)b * SSQ;
    float v[SSQ / 256];
    float m = -1e30f;
#pragma unroll
    for (int i = 0; i < SSQ / 256; i++) {
        v[i] = sc[t + 256 * i];
        m = fmaxf(m, v[i]);
    }
#pragma unroll
    for (int off = 16; off; off >>= 1) m = fmaxf(m, __shfl_xor_sync(0xffffffffu, m, off));
    if ((t & 31) == 0) sred[t >> 5] = m;
    __syncthreads();
    float M = sred[0];
#pragma unroll
    for (int j = 1; j < 8; j++) M = fmaxf(M, sred[j]);

    float sum = 0.f;
#pragma unroll
    for (int i = 0; i < SSQ / 256; i++) {
        float e = __expf(v[i] - M);
        v[i] = e;
        sum += e;
    }
#pragma unroll
    for (int off = 16; off; off >>= 1) sum += __shfl_xor_sync(0xffffffffu, sum, off);
    if ((t & 31) == 0) sred[32 + (t >> 5)] = sum;
    __syncthreads();
    float T = 0.f;
#pragma unroll
    for (int j = 0; j < 8; j++) T += sred[32 + j];
    float inv = 1.f / T;
#pragma unroll
    for (int i = 0; i < SSQ / 256; i++) {
        float wgt = v[i] * inv;
        sc[t + 256 * i] = wgt;
        if (wout) wout[(size_t)b * SSQ + t + 256 * i] = wgt;
    }
}

// -------- context[b][h] = sum_s w[b][s] * keys[b][s][h] --------
__global__ void context_kernel(const float* __restrict__ keys, float* __restrict__ ctx) {
    int b = blockIdx.x;
    int h = threadIdx.x;  // 512 threads
    __shared__ float w[SSQ];
    for (int i = h; i < SSQ; i += HD) w[i] = g_scores[(size_t)b * SSQ + i];
    __syncthreads();
    if (!ctx) return;
    float acc = 0.f;
    const float* kb = keys + (size_t)b * SSQ * HD + h;
#pragma unroll 8
    for (int s = 0; s < SSQ; s++) acc += w[s] * kb[(size_t)s * HD];
    ctx[(size_t)b * HD + h] = acc;
}

extern "C" void kernel_launch(void* const* d_in, const int* in_sizes, int n_in,
                              void* d_out, int out_size) {
    const float* query = (const float*)d_in[0];
    const float* keys  = (const float*)d_in[1];
    const float* Wa    = (const float*)d_in[2];
    const float* ba    = (const float*)d_in[3];
    const float* Ua    = (const float*)d_in[4];
    const float* bu    = (const float*)d_in[5];
    const float* Va    = (const float*)d_in[6];
    const float* bv    = (const float*)d_in[7];
    float* out = (float*)d_out;

    // Default: tuple (context, weights) flattened, context first.
    float* ctx_out = out;
    float* w_out = out + BB * HD;
    if (out_size == BB * SSQ) { ctx_out = nullptr; w_out = out; }      // weights only
    else if (out_size == BB * HD) { w_out = nullptr; }                 // context only

    cudaFuncSetAttribute(scores_kernel, cudaFuncAttributeMaxDynamicSharedMemorySize,
                         TSR * HD * 8);

    dim3 tb(32, 8);
    transpose512<<<dim3(16, 16), tb>>>(Wa, 0);
    transpose512<<<dim3(16, 16), tb>>>(Ua, 1);
    c_kernel<<<BB, HD>>>(query, ba, bu);
    scores_kernel<<<dim3(SSQ / TSR, BB), NTH, TSR * HD * 8>>>(keys, Va, bv);
    softmax_kernel<<<BB, 256>>>(w_out);
    context_kernel<<<BB, HD>>>(keys, ctx_out);
}

// round 3
// speedup vs baseline: 3.9803x; 3.9803x over previous
#include <cuda_runtime.h>
#include <cuda_fp16.h>
#include <cstdint>
#include <math.h>

#define HD 512
#define BB 128
#define SSQ 2048
#define MT 128       // s-rows per block
#define NTILE 256    // n-cols per block (half of HD)
#define KC 32
#define NCH (HD / KC)  // 16
#define ROWB 80        // padded smem row bytes (40 fp16, 64 valid)

// smem map (bytes): two 40KB buffers, then partials, then cv
//   buffer: A_hi [128][80] @0, A_lo @10240, B [256][80] @20480
#define PLANE 10240
#define OF_B 20480
#define BUFSZ 40960
#define OF_PART (2 * BUFSZ)          // 81920, float[4][128] = 2KB
#define OF_CV (OF_PART + 2048)       // float2[256] = 2KB
#define SMEM_TOTAL (OF_CV + 2048)    // 86016

// ---------------- device scratch ----------------
__device__ float g_WaT[HD * HD];
__device__ float g_c[BB * HD];
__device__ float g_scores[BB * SSQ];
__device__ float g_part[2][BB * SSQ];
__device__ __align__(16) __half g_UaP[(size_t)NCH * HD * 40];  // [kc][n][40]

// ---------------- helpers ----------------
__device__ __forceinline__ uint32_t smem_u32(const void* p) {
    uint32_t a;
    asm("{ .reg .u64 t; cvta.to.shared.u64 t, %1; cvt.u32.u64 %0, t; }" : "=r"(a) : "l"(p));
    return a;
}
__device__ __forceinline__ void cpasync16(uint32_t dst, const void* src) {
    asm volatile("cp.async.cg.shared.global [%0], [%1], 16;" :: "r"(dst), "l"(src));
}
__device__ __forceinline__ void cpasync_commit() {
    asm volatile("cp.async.commit_group;" ::: "memory");
}
__device__ __forceinline__ void cpasync_waitall() {
    asm volatile("cp.async.wait_group 0;" ::: "memory");
}
__device__ __forceinline__ void ldsm4(uint32_t (&r)[4], uint32_t addr) {
    asm volatile("ldmatrix.sync.aligned.m8n8.x4.shared.b16 {%0,%1,%2,%3}, [%4];"
                 : "=r"(r[0]), "=r"(r[1]), "=r"(r[2]), "=r"(r[3]) : "r"(addr));
}
__device__ __forceinline__ void mma16816(float (&d)[4], const uint32_t (&a)[4],
                                         uint32_t b0, uint32_t b1) {
    asm volatile(
        "mma.sync.aligned.m16n8k16.row.col.f32.f16.f16.f32 "
        "{%0,%1,%2,%3}, {%4,%5,%6,%7}, {%8,%9}, {%0,%1,%2,%3};"
        : "+f"(d[0]), "+f"(d[1]), "+f"(d[2]), "+f"(d[3])
        : "r"(a[0]), "r"(a[1]), "r"(a[2]), "r"(a[3]), "r"(b0), "r"(b1));
}

// ---------------- prep kernels ----------------
__global__ void transpose512(const float* __restrict__ in) {
    __shared__ float tile[32][33];
    int bx = blockIdx.x * 32, by = blockIdx.y * 32;
    int tx = threadIdx.x, ty = threadIdx.y;  // (32,8)
#pragma unroll
    for (int i = 0; i < 32; i += 8)
        tile[ty + i][tx] = in[(size_t)(by + ty + i) * HD + bx + tx];
    __syncthreads();
#pragma unroll
    for (int i = 0; i < 32; i += 8)
        g_WaT[(size_t)(bx + ty + i) * HD + by + tx] = tile[tx][ty + i];
}

__global__ void ua_prep(const float* __restrict__ Ua) {
    int n = blockIdx.x;   // 512
    int k = threadIdx.x;  // 512
    float u = Ua[(size_t)n * HD + k];
    g_UaP[((size_t)(k >> 5) * HD + n) * 40 + (k & 31)] = __float2half_rn(u);
}

__global__ void c_kernel(const float* __restrict__ query, const float* __restrict__ ba,
                         const float* __restrict__ bu) {
    int b = blockIdx.x;
    int o = threadIdx.x;  // 512
    __shared__ float q[HD];
    q[o] = query[(size_t)b * HD + o];
    __syncthreads();
    float acc = ba[o] + bu[o];
#pragma unroll 8
    for (int h = 0; h < HD; h++) acc += q[h] * g_WaT[(size_t)h * HD + o];
    g_c[(size_t)b * HD + o] = acc;
}

// ---------------- GEMM pieces ----------------
__device__ __forceinline__ void loadA_regs(float4 (&v)[4], const float* __restrict__ keysB,
                                           int kc, int r, int kq) {
    const float* src = keysB + (size_t)r * HD + kc * KC + kq;
    v[0] = *(const float4*)(src);
    v[1] = *(const float4*)(src + 4);
    v[2] = *(const float4*)(src + 8);
    v[3] = *(const float4*)(src + 12);
}
__device__ __forceinline__ void convert_storeA(const float4 (&v)[4], unsigned char* buf,
                                               int r, int kq) {
    const float* f = (const float*)v;
    __half h[16], l[16];
#pragma unroll
    for (int i = 0; i < 16; i++) {
        __half hh = __float2half_rn(f[i]);
        h[i] = hh;
        l[i] = __float2half_rn(f[i] - __half2float(hh));
    }
    uint4* dhi = (uint4*)(buf + r * ROWB + kq * 2);
    uint4* dlo = (uint4*)(buf + PLANE + r * ROWB + kq * 2);
    dhi[0] = ((const uint4*)h)[0];
    dhi[1] = ((const uint4*)h)[1];
    dlo[0] = ((const uint4*)l)[0];
    dlo[1] = ((const uint4*)l)[1];
}
__device__ __forceinline__ void loadB(uint32_t dstB, const __half* __restrict__ src, int tid) {
    const unsigned char* s = (const unsigned char*)src;
#pragma unroll
    for (int i = tid; i < NTILE * 5; i += 256)
        cpasync16(dstB + i * 16, s + i * 16);
}

__global__ void __launch_bounds__(256, 1)
gemm_scores_kernel(const float* __restrict__ keys, const float* __restrict__ Va) {
    extern __shared__ unsigned char smem[];
    uint32_t sb = smem_u32(smem);
    int tid = threadIdx.x, lid = tid & 31, wid = tid >> 5;
    int s0 = blockIdx.x * MT, b = blockIdx.y, nh = blockIdx.z;
    const float* keysB = keys + ((size_t)b * SSQ + s0) * HD;
    int wm = wid & 1, wn = wid >> 1;       // warp tile (wm*64, wn*64)
    int r = tid >> 1, kq = (tid & 1) * 16; // A-conversion assignment

    // stage {c, Va} for this n-half
    {
        float2* cv = (float2*)(smem + OF_CV);
        cv[tid] = make_float2(g_c[(size_t)b * HD + nh * NTILE + tid],
                              Va[nh * NTILE + tid]);
    }

    // prologue: chunk 0 in flight, chunk 1 key-regs in flight
    float4 vr[4];
    loadA_regs(vr, keysB, 0, r, kq);
    loadB(sb + OF_B, g_UaP + ((size_t)0 * HD + nh * NTILE) * 40, tid);
    cpasync_commit();
    convert_storeA(vr, smem, r, kq);
    loadA_regs(vr, keysB, 1, r, kq);
    cpasync_waitall();
    __syncthreads();

    float acc[4][8][4];
#pragma unroll
    for (int i = 0; i < 4; i++)
#pragma unroll
        for (int j = 0; j < 8; j++)
#pragma unroll
            for (int c = 0; c < 4; c++) acc[i][j][c] = 0.f;

    uint32_t aoff = (lid & 15) * ROWB + (lid >> 4) * 16;

    for (int kc = 0; kc < NCH; kc++) {
        uint32_t curs = sb + (uint32_t)(kc & 1) * BUFSZ;
        if (kc + 1 < NCH) {
            unsigned char* nxt = smem + ((kc + 1) & 1) * BUFSZ;
            loadB(sb + (uint32_t)((kc + 1) & 1) * BUFSZ + OF_B,
                  g_UaP + ((size_t)(kc + 1) * HD + nh * NTILE) * 40, tid);
            cpasync_commit();
            convert_storeA(vr, nxt, r, kq);
            if (kc + 2 < NCH) loadA_regs(vr, keysB, kc + 2, r, kq);
        }
#pragma unroll
        for (int ks = 0; ks < 2; ks++) {
            uint32_t kb = ks * 32;
            uint32_t ah[4][4], al[4][4], bb4[4][4];
#pragma unroll
            for (int i = 0; i < 4; i++) {
                uint32_t base = curs + (wm * 64 + i * 16) * ROWB + aoff + kb;
                ldsm4(ah[i], base);
                ldsm4(al[i], base + PLANE);
            }
#pragma unroll
            for (int j2 = 0; j2 < 4; j2++)
                ldsm4(bb4[j2], curs + OF_B + (wn * 64 + j2 * 16) * ROWB + aoff + kb);
#pragma unroll
            for (int i = 0; i < 4; i++)
#pragma unroll
                for (int j2 = 0; j2 < 4; j2++) {
                    mma16816(acc[i][2 * j2], ah[i], bb4[j2][0], bb4[j2][2]);
                    mma16816(acc[i][2 * j2 + 1], ah[i], bb4[j2][1], bb4[j2][3]);
                    mma16816(acc[i][2 * j2], al[i], bb4[j2][0], bb4[j2][2]);
                    mma16816(acc[i][2 * j2 + 1], al[i], bb4[j2][1], bb4[j2][3]);
                }
        }
        if (kc + 1 < NCH) {
            cpasync_waitall();
            __syncthreads();
        }
    }

    // epilogue: score_part[row] = sum_o Va[o]*tanh(D[row][o] + c[o])
    float* part = (float*)(smem + OF_PART);
    const float2* cv = (const float2*)(smem + OF_CV);
#pragma unroll
    for (int i = 0; i < 4; i++) {
        float sA = 0.f, sB = 0.f;
#pragma unroll
        for (int j = 0; j < 8; j++) {
            int ol = wn * 64 + j * 8 + (lid & 3) * 2;
            float2 c0 = cv[ol], c1 = cv[ol + 1];
            sA += c0.y * tanhf(acc[i][j][0] + c0.x);
            sA += c1.y * tanhf(acc[i][j][1] + c1.x);
            sB += c0.y * tanhf(acc[i][j][2] + c0.x);
            sB += c1.y * tanhf(acc[i][j][3] + c1.x);
        }
        sA += __shfl_xor_sync(0xffffffffu, sA, 1);
        sA += __shfl_xor_sync(0xffffffffu, sA, 2);
        sB += __shfl_xor_sync(0xffffffffu, sB, 1);
        sB += __shfl_xor_sync(0xffffffffu, sB, 2);
        if ((lid & 3) == 0) {
            int row = wm * 64 + i * 16 + (lid >> 2);
            part[wn * 128 + row] = sA;
            part[wn * 128 + row + 8] = sB;
        }
    }
    __syncthreads();
    if (tid < MT) {
        float v = part[tid] + part[128 + tid] + part[256 + tid] + part[384 + tid];
        g_part[nh][(size_t)b * SSQ + s0 + tid] = v;
    }
}

// ---------------- softmax (sums the two n-half partial planes) ----------------
__global__ void softmax_kernel(float* __restrict__ wout) {
    int b = blockIdx.x, t = threadIdx.x;  // 256 threads
    __shared__ float sred[64];
    size_t base = (size_t)b * SSQ;
    float v[SSQ / 256];
    float m = -1e30f;
#pragma unroll
    for (int i = 0; i < SSQ / 256; i++) {
        v[i] = g_part[0][base + t + 256 * i] + g_part[1][base + t + 256 * i];
        m = fmaxf(m, v[i]);
    }
#pragma unroll
    for (int off = 16; off; off >>= 1) m = fmaxf(m, __shfl_xor_sync(0xffffffffu, m, off));
    if ((t & 31) == 0) sred[t >> 5] = m;
    __syncthreads();
    float M = sred[0];
#pragma unroll
    for (int j = 1; j < 8; j++) M = fmaxf(M, sred[j]);
    float sum = 0.f;
#pragma unroll
    for (int i = 0; i < SSQ / 256; i++) {
        float e = __expf(v[i] - M);
        v[i] = e;
        sum += e;
    }
#pragma unroll
    for (int off = 16; off; off >>= 1) sum += __shfl_xor_sync(0xffffffffu, sum, off);
    if ((t & 31) == 0) sred[32 + (t >> 5)] = sum;
    __syncthreads();
    float T = 0.f;
#pragma unroll
    for (int j = 0; j < 8; j++) T += sred[32 + j];
    float inv = 1.f / T;
#pragma unroll
    for (int i = 0; i < SSQ / 256; i++) {
        float wgt = v[i] * inv;
        g_scores[base + t + 256 * i] = wgt;
        if (wout) wout[base + t + 256 * i] = wgt;
    }
}

// ---------------- context[b][h] = sum_s w[b][s]*keys[b][s][h] ----------------
__global__ void context_kernel(const float* __restrict__ keys, float* __restrict__ ctx) {
    int b = blockIdx.x;
    int h = threadIdx.x;  // 512
    __shared__ float w[SSQ];
    for (int i = h; i < SSQ; i += HD) w[i] = g_scores[(size_t)b * SSQ + i];
    __syncthreads();
    if (!ctx) return;
    float acc = 0.f;
    const float* kb = keys + (size_t)b * SSQ * HD + h;
#pragma unroll 8
    for (int s = 0; s < SSQ; s++) acc += w[s] * kb[(size_t)s * HD];
    ctx[(size_t)b * HD + h] = acc;
}

extern "C" void kernel_launch(void* const* d_in, const int* in_sizes, int n_in,
                              void* d_out, int out_size) {
    const float* query = (const float*)d_in[0];
    const float* keys  = (const float*)d_in[1];
    const float* Wa    = (const float*)d_in[2];
    const float* ba    = (const float*)d_in[3];
    const float* Ua    = (const float*)d_in[4];
    const float* bu    = (const float*)d_in[5];
    const float* Va    = (const float*)d_in[6];
    float* out = (float*)d_out;

    float* ctx_out = out;
    float* w_out = out + BB * HD;
    if (out_size == BB * SSQ) { ctx_out = nullptr; w_out = out; }
    else if (out_size == BB * HD) { w_out = nullptr; }

    static int smem_set = 0;
    if (!smem_set) {
        cudaFuncSetAttribute(gemm_scores_kernel,
                             cudaFuncAttributeMaxDynamicSharedMemorySize, SMEM_TOTAL);
        smem_set = 1;
    }

    transpose512<<<dim3(16, 16), dim3(32, 8)>>>(Wa);
    ua_prep<<<HD, HD>>>(Ua);
    c_kernel<<<BB, HD>>>(query, ba, bu);
    gemm_scores_kernel<<<dim3(SSQ / MT, BB, 2), 256, SMEM_TOTAL>>>(keys, Va);
    softmax_kernel<<<BB, 256>>>(w_out);
    context_kernel<<<BB, HD>>>(keys, ctx_out);
}

// round 4
// speedup vs baseline: 6.5397x; 1.6430x over previous
#include <cuda_runtime.h>
#include <cuda_fp16.h>
#include <cstdint>
#include <math.h>

#define HD 512
#define BB 128
#define SSQ 2048
#define MT 128        // s-rows per block
#define NTILE 256     // n-cols per block (half of HD)
#define KC 32
#define NCH (HD / KC) // 16
#define ROWB 80       // padded smem row bytes (40 fp16, 64 valid)
#define GT 512        // gemm threads

// smem: two 30KB buffers { A[128][80] @0, B[256][80] @10240 }, then partials, cv
#define OF_B 10240
#define BUFSZ 30720
#define OF_PART (2 * BUFSZ)           // 61440, float[8][128] = 4KB
#define OF_CV (OF_PART + 4096)        // 65536, float2[256] = 2KB
#define SMEM_TOTAL (OF_CV + 2048)     // 67584

// ---------------- device scratch ----------------
__device__ float g_WaT[HD * HD];
__device__ float g_c[BB * HD];
__device__ float g_scores[BB * SSQ];
__device__ float g_part[2][BB * SSQ];
__device__ float g_cpart[4][BB * HD];
__device__ __align__(16) __half g_UaP[(size_t)NCH * HD * 40];  // [kc][n][40]

// ---------------- helpers ----------------
__device__ __forceinline__ uint32_t smem_u32(const void* p) {
    uint32_t a;
    asm("{ .reg .u64 t; cvta.to.shared.u64 t, %1; cvt.u32.u64 %0, t; }" : "=r"(a) : "l"(p));
    return a;
}
__device__ __forceinline__ void cpasync16(uint32_t dst, const void* src) {
    asm volatile("cp.async.cg.shared.global [%0], [%1], 16;" :: "r"(dst), "l"(src));
}
__device__ __forceinline__ void cpasync_commit() {
    asm volatile("cp.async.commit_group;" ::: "memory");
}
__device__ __forceinline__ void cpasync_waitall() {
    asm volatile("cp.async.wait_group 0;" ::: "memory");
}
__device__ __forceinline__ void ldsm4(uint32_t (&r)[4], uint32_t addr) {
    asm volatile("ldmatrix.sync.aligned.m8n8.x4.shared.b16 {%0,%1,%2,%3}, [%4];"
                 : "=r"(r[0]), "=r"(r[1]), "=r"(r[2]), "=r"(r[3]) : "r"(addr));
}
__device__ __forceinline__ void mma16816(float (&d)[4], const uint32_t (&a)[4],
                                         uint32_t b0, uint32_t b1) {
    asm volatile(
        "mma.sync.aligned.m16n8k16.row.col.f32.f16.f16.f32 "
        "{%0,%1,%2,%3}, {%4,%5,%6,%7}, {%8,%9}, {%0,%1,%2,%3};"
        : "+f"(d[0]), "+f"(d[1]), "+f"(d[2]), "+f"(d[3])
        : "r"(a[0]), "r"(a[1]), "r"(a[2]), "r"(a[3]), "r"(b0), "r"(b1));
}

// ---------------- prep kernels ----------------
__global__ void transpose512(const float* __restrict__ in) {
    __shared__ float tile[32][33];
    int bx = blockIdx.x * 32, by = blockIdx.y * 32;
    int tx = threadIdx.x, ty = threadIdx.y;  // (32,8)
#pragma unroll
    for (int i = 0; i < 32; i += 8)
        tile[ty + i][tx] = in[(size_t)(by + ty + i) * HD + bx + tx];
    __syncthreads();
#pragma unroll
    for (int i = 0; i < 32; i += 8)
        g_WaT[(size_t)(bx + ty + i) * HD + by + tx] = tile[tx][ty + i];
}

__global__ void ua_prep(const float* __restrict__ Ua) {
    int n = blockIdx.x;   // 512
    int k = threadIdx.x;  // 512
    float u = Ua[(size_t)n * HD + k];
    g_UaP[((size_t)(k >> 5) * HD + n) * 40 + (k & 31)] = __float2half_rn(u);
}

__global__ void c_kernel(const float* __restrict__ query, const float* __restrict__ ba,
                         const float* __restrict__ bu) {
    int b = blockIdx.x;
    int o = threadIdx.x;  // 512
    __shared__ float q[HD];
    q[o] = query[(size_t)b * HD + o];
    __syncthreads();
    float acc = ba[o] + bu[o];
#pragma unroll 8
    for (int h = 0; h < HD; h++) acc += q[h] * g_WaT[(size_t)h * HD + o];
    g_c[(size_t)b * HD + o] = acc;
}

// ---------------- GEMM pieces ----------------
__device__ __forceinline__ void loadA_regs(float4 (&v)[2], const float* __restrict__ keysB,
                                           int kc, int r, int kq) {
    const float* src = keysB + (size_t)r * HD + kc * KC + kq;
    v[0] = *(const float4*)(src);
    v[1] = *(const float4*)(src + 4);
}
__device__ __forceinline__ void convert_storeA(const float4 (&v)[2], unsigned char* buf,
                                               int r, int kq) {
    const float* f = (const float*)v;
    __half h[8];
#pragma unroll
    for (int i = 0; i < 8; i++) h[i] = __float2half_rn(f[i]);
    *(uint4*)(buf + r * ROWB + kq * 2) = *(const uint4*)h;
}
__device__ __forceinline__ void loadB(uint32_t dstB, const __half* __restrict__ src, int tid) {
    const unsigned char* s = (const unsigned char*)src;
#pragma unroll
    for (int i = tid; i < NTILE * 5; i += GT)
        cpasync16(dstB + i * 16, s + i * 16);
}

__global__ void __launch_bounds__(GT, 1)
gemm_scores_kernel(const float* __restrict__ keys, const float* __restrict__ Va) {
    extern __shared__ unsigned char smem[];
    uint32_t sb = smem_u32(smem);
    int tid = threadIdx.x, lid = tid & 31, wid = tid >> 5;
    int s0 = blockIdx.x * MT, b = blockIdx.y, nh = blockIdx.z;
    const float* keysB = keys + ((size_t)b * SSQ + s0) * HD;
    int wm = wid & 1, wn = wid >> 1;        // warp tile (wm*64 rows, wn*32 cols)
    int r = tid >> 2, kq = (tid & 3) * 8;   // A-conversion assignment

    // stage {c, Va} for this n-half
    if (tid < NTILE) {
        float2* cv = (float2*)(smem + OF_CV);
        cv[tid] = make_float2(g_c[(size_t)b * HD + nh * NTILE + tid],
                              Va[nh * NTILE + tid]);
    }

    // prologue
    float4 vr[2];
    loadA_regs(vr, keysB, 0, r, kq);
    loadB(sb + OF_B, g_UaP + ((size_t)0 * HD + nh * NTILE) * 40, tid);
    cpasync_commit();
    convert_storeA(vr, smem, r, kq);
    loadA_regs(vr, keysB, 1, r, kq);
    cpasync_waitall();
    __syncthreads();

    float acc[4][4][4];
#pragma unroll
    for (int i = 0; i < 4; i++)
#pragma unroll
        for (int j = 0; j < 4; j++)
#pragma unroll
            for (int c = 0; c < 4; c++) acc[i][j][c] = 0.f;

    uint32_t aoff = (lid & 15) * ROWB + (lid >> 4) * 16;

    for (int kc = 0; kc < NCH; kc++) {
        uint32_t curs = sb + (uint32_t)(kc & 1) * BUFSZ;
        if (kc + 1 < NCH) {
            unsigned char* nxt = smem + ((kc + 1) & 1) * BUFSZ;
            loadB(sb + (uint32_t)((kc + 1) & 1) * BUFSZ + OF_B,
                  g_UaP + ((size_t)(kc + 1) * HD + nh * NTILE) * 40, tid);
            cpasync_commit();
            convert_storeA(vr, nxt, r, kq);
            if (kc + 2 < NCH) loadA_regs(vr, keysB, kc + 2, r, kq);
        }
#pragma unroll
        for (int ks = 0; ks < 2; ks++) {
            uint32_t kb = ks * 32;
            uint32_t ah[4][4], bb[2][4];
#pragma unroll
            for (int i = 0; i < 4; i++)
                ldsm4(ah[i], curs + (wm * 64 + i * 16) * ROWB + aoff + kb);
#pragma unroll
            for (int j2 = 0; j2 < 2; j2++)
                ldsm4(bb[j2], curs + OF_B + (wn * 32 + j2 * 16) * ROWB + aoff + kb);
#pragma unroll
            for (int i = 0; i < 4; i++)
#pragma unroll
                for (int j2 = 0; j2 < 2; j2++) {
                    mma16816(acc[i][2 * j2], ah[i], bb[j2][0], bb[j2][2]);
                    mma16816(acc[i][2 * j2 + 1], ah[i], bb[j2][1], bb[j2][3]);
                }
        }
        if (kc + 1 < NCH) {
            cpasync_waitall();
            __syncthreads();
        }
    }

    // epilogue: part[wn][row] = sum_{o in warp cols} Va[o]*tanh(D[row][o]+c[o])
    float* part = (float*)(smem + OF_PART);
    const float2* cv = (const float2*)(smem + OF_CV);
#pragma unroll
    for (int i = 0; i < 4; i++) {
        float sA = 0.f, sB = 0.f;
#pragma unroll
        for (int j = 0; j < 4; j++) {
            int ol = wn * 32 + j * 8 + (lid & 3) * 2;
            float2 c0 = cv[ol], c1 = cv[ol + 1];
            sA += c0.y * tanhf(acc[i][j][0] + c0.x);
            sA += c1.y * tanhf(acc[i][j][1] + c1.x);
            sB += c0.y * tanhf(acc[i][j][2] + c0.x);
            sB += c1.y * tanhf(acc[i][j][3] + c1.x);
        }
        sA += __shfl_xor_sync(0xffffffffu, sA, 1);
        sA += __shfl_xor_sync(0xffffffffu, sA, 2);
        sB += __shfl_xor_sync(0xffffffffu, sB, 1);
        sB += __shfl_xor_sync(0xffffffffu, sB, 2);
        if ((lid & 3) == 0) {
            int row = wm * 64 + i * 16 + (lid >> 2);
            part[wn * 128 + row] = sA;
            part[wn * 128 + row + 8] = sB;
        }
    }
    __syncthreads();
    if (tid < MT) {
        float v = 0.f;
#pragma unroll
        for (int p = 0; p < 8; p++) v += part[p * 128 + tid];
        g_part[nh][(size_t)b * SSQ + s0 + tid] = v;
    }
}

// ---------------- softmax (sums the two n-half partial planes) ----------------
__global__ void softmax_kernel(float* __restrict__ wout) {
    int b = blockIdx.x, t = threadIdx.x;  // 256 threads
    __shared__ float sred[64];
    size_t base = (size_t)b * SSQ;
    float v[SSQ / 256];
    float m = -1e30f;
#pragma unroll
    for (int i = 0; i < SSQ / 256; i++) {
        v[i] = g_part[0][base + t + 256 * i] + g_part[1][base + t + 256 * i];
        m = fmaxf(m, v[i]);
    }
#pragma unroll
    for (int off = 16; off; off >>= 1) m = fmaxf(m, __shfl_xor_sync(0xffffffffu, m, off));
    if ((t & 31) == 0) sred[t >> 5] = m;
    __syncthreads();
    float M = sred[0];
#pragma unroll
    for (int j = 1; j < 8; j++) M = fmaxf(M, sred[j]);
    float sum = 0.f;
#pragma unroll
    for (int i = 0; i < SSQ / 256; i++) {
        float e = __expf(v[i] - M);
        v[i] = e;
        sum += e;
    }
#pragma unroll
    for (int off = 16; off; off >>= 1) sum += __shfl_xor_sync(0xffffffffu, sum, off);
    if ((t & 31) == 0) sred[32 + (t >> 5)] = sum;
    __syncthreads();
    float T = 0.f;
#pragma unroll
    for (int j = 0; j < 8; j++) T += sred[32 + j];
    float inv = 1.f / T;
#pragma unroll
    for (int i = 0; i < SSQ / 256; i++) {
        float wgt = v[i] * inv;
        g_scores[base + t + 256 * i] = wgt;
        if (wout) wout[base + t + 256 * i] = wgt;
    }
}

// ---------------- context, split 4-way over s ----------------
__global__ void context_part_kernel(const float* __restrict__ keys) {
    int b = blockIdx.x, q = blockIdx.y;
    int h = threadIdx.x;  // 512
    __shared__ float w[SSQ / 4];
    for (int i = h; i < SSQ / 4; i += HD) w[i] = g_scores[(size_t)b * SSQ + q * (SSQ / 4) + i];
    __syncthreads();
    float acc = 0.f;
    const float* kb = keys + ((size_t)b * SSQ + q * (SSQ / 4)) * HD + h;
#pragma unroll 8
    for (int s = 0; s < SSQ / 4; s++) acc += w[s] * kb[(size_t)s * HD];
    g_cpart[q][(size_t)b * HD + h] = acc;
}
__global__ void context_combine_kernel(float* __restrict__ ctx) {
    int b = blockIdx.x, h = threadIdx.x;
    size_t i = (size_t)b * HD + h;
    ctx[i] = g_cpart[0][i] + g_cpart[1][i] + g_cpart[2][i] + g_cpart[3][i];
}

extern "C" void kernel_launch(void* const* d_in, const int* in_sizes, int n_in,
                              void* d_out, int out_size) {
    const float* query = (const float*)d_in[0];
    const float* keys  = (const float*)d_in[1];
    const float* Wa    = (const float*)d_in[2];
    const float* ba    = (const float*)d_in[3];
    const float* Ua    = (const float*)d_in[4];
    const float* bu    = (const float*)d_in[5];
    const float* Va    = (const float*)d_in[6];
    float* out = (float*)d_out;

    float* ctx_out = out;
    float* w_out = out + BB * HD;
    if (out_size == BB * SSQ) { ctx_out = nullptr; w_out = out; }
    else if (out_size == BB * HD) { w_out = nullptr; }

    static int smem_set = 0;
    if (!smem_set) {
        cudaFuncSetAttribute(gemm_scores_kernel,
                             cudaFuncAttributeMaxDynamicSharedMemorySize, SMEM_TOTAL);
        smem_set = 1;
    }

    transpose512<<<dim3(16, 16), dim3(32, 8)>>>(Wa);
    ua_prep<<<HD, HD>>>(Ua);
    c_kernel<<<BB, HD>>>(query, ba, bu);
    gemm_scores_kernel<<<dim3(SSQ / MT, BB, 2), GT, SMEM_TOTAL>>>(keys, Va);
    softmax_kernel<<<BB, 256>>>(w_out);
    context_part_kernel<<<dim3(BB, 4), HD>>>(keys);
    if (ctx_out) context_combine_kernel<<<BB, HD>>>(ctx_out);
}